// round 11
// baseline (speedup 1.0000x reference)
#include <cuda_runtime.h>
#include <cuda_bf16.h>

// Problem constants
#define BB 4
#define SS 4096
#define DD 256
#define HH 4
#define HD 64
#define SCALE 0.125f   // 64^-0.5

// Scratch (allocation-free rule: __device__ globals)
__device__ float g_q[BB*HH*SS*HD];
__device__ float g_k[BB*HH*SS*HD];
__device__ float g_v[BB*HH*SS*HD];
__device__ float g_ao[BB*HH*SS*HD];

// ---------------------------------------------------------------------------
// GEMM: C[m,n] = sum_k A[m,k] * W[n,k] (+ bias[n])
// M = 16384 (m = b*SS + s), N = 256, K = 256.
// HSA: A is head-split [B,H,S,HD] (k -> h= k/64, d = k%64)
// HSC: C written head-split [B,H,S,HD] (n -> h = n/64, d = n%64)
// Block: 256 threads, 64x64 output tile, 4x4 per-thread micro-tile.
// ---------------------------------------------------------------------------
template<bool HSA, bool HSC, bool BIAS>
__global__ void __launch_bounds__(256) gemm_kernel(
    const float* __restrict__ A, const float* __restrict__ W,
    const float* __restrict__ bias, float* __restrict__ C)
{
    __shared__ float As[64][68];
    __shared__ float Wsh[64][68];

    const int tid = threadIdx.x;
    const int tx = tid & 15;        // 0..15
    const int ty = tid >> 4;        // 0..15
    const int m0 = blockIdx.x * 64;
    const int n0 = blockIdx.y * 64;
    const int lr = ty;              // loader row base
    const int lc = tx * 4;          // loader col

    float acc[4][4] = {};

    for (int kc = 0; kc < 256; kc += 64) {
        #pragma unroll
        for (int rr = 0; rr < 4; rr++) {
            const int row = lr + rr * 16;
            // A tile
            const int m = m0 + row;
            const float* asrc;
            if (HSA) {
                const int b = m >> 12, s = m & 4095;
                const int h = kc >> 6;
                asrc = A + (((b * HH + h) * SS + s) * HD + lc);
            } else {
                asrc = A + ((size_t)m * 256 + kc + lc);
            }
            float4 va = *(const float4*)asrc;
            As[row][lc + 0] = va.x; As[row][lc + 1] = va.y;
            As[row][lc + 2] = va.z; As[row][lc + 3] = va.w;
            // W tile: row n0+row, cols kc+lc
            float4 vw = *(const float4*)(W + (size_t)(n0 + row) * 256 + kc + lc);
            Wsh[row][lc + 0] = vw.x; Wsh[row][lc + 1] = vw.y;
            Wsh[row][lc + 2] = vw.z; Wsh[row][lc + 3] = vw.w;
        }
        __syncthreads();

        const int r0 = ty * 4, c0 = tx * 4;
        #pragma unroll 16
        for (int k = 0; k < 64; k++) {
            float a[4], w[4];
            #pragma unroll
            for (int i = 0; i < 4; i++) a[i] = As[r0 + i][k];
            #pragma unroll
            for (int j = 0; j < 4; j++) w[j] = Wsh[c0 + j][k];
            #pragma unroll
            for (int i = 0; i < 4; i++)
                #pragma unroll
                for (int j = 0; j < 4; j++)
                    acc[i][j] = fmaf(a[i], w[j], acc[i][j]);
        }
        __syncthreads();
    }

    const int r0 = ty * 4, c0 = tx * 4;
    #pragma unroll
    for (int i = 0; i < 4; i++) {
        const int m = m0 + r0 + i;
        #pragma unroll
        for (int j = 0; j < 4; j++) {
            const int n = n0 + c0 + j;
            float v = acc[i][j];
            if (BIAS) v += bias[n];
            if (HSC) {
                const int b = m >> 12, s = m & 4095;
                const int h = n >> 6, d = n & 63;
                C[((b * HH + h) * SS + s) * HD + d] = v;
            } else {
                C[(size_t)m * 256 + n] = v;
            }
        }
    }
}

// ---------------------------------------------------------------------------
// Flash attention: one block = 64 queries for one (b, h).
// Tiles: Q[64][64] persistent, K[64][64] (re-used as P after scores), V[64][64].
// 256 threads, 4x4 micro-tiles, warp-shuffle row reductions (16-lane groups).
// ---------------------------------------------------------------------------
__global__ void __launch_bounds__(256) attn_kernel(
    const float* __restrict__ Q, const float* __restrict__ K,
    const float* __restrict__ V, float* __restrict__ O)
{
    extern __shared__ float sm[];
    float (*Qs)[68] = (float (*)[68])sm;
    float (*Ks)[68] = (float (*)[68])(sm + 64 * 68);       // re-used as P
    float (*Vs)[68] = (float (*)[68])(sm + 2 * 64 * 68);

    const int tid = threadIdx.x;
    const int tx = tid & 15, ty = tid >> 4;
    const int qt = blockIdx.x;     // query tile
    const int h  = blockIdx.y;
    const int b  = blockIdx.z;
    const int bh = b * HH + h;
    const float* qbase = Q + ((size_t)bh * SS) * HD;
    const float* kbase = K + ((size_t)bh * SS) * HD;
    const float* vbase = V + ((size_t)bh * SS) * HD;

    const int lr = ty, lc = tx * 4;
    const int r0 = ty * 4, c0 = tx * 4;

    // Load Q tile (rows qt*64 .. +63)
    #pragma unroll
    for (int rr = 0; rr < 4; rr++) {
        const int row = lr + rr * 16;
        float4 vq = *(const float4*)(qbase + (size_t)(qt * 64 + row) * HD + lc);
        Qs[row][lc + 0] = vq.x; Qs[row][lc + 1] = vq.y;
        Qs[row][lc + 2] = vq.z; Qs[row][lc + 3] = vq.w;
    }

    float mi[4], li[4], o[4][4];
    #pragma unroll
    for (int i = 0; i < 4; i++) {
        mi[i] = -1e30f; li[i] = 0.f;
        #pragma unroll
        for (int j = 0; j < 4; j++) o[i][j] = 0.f;
    }
    __syncthreads();

    for (int kb = 0; kb < SS / 64; kb++) {
        // Load K, V tiles
        #pragma unroll
        for (int rr = 0; rr < 4; rr++) {
            const int row = lr + rr * 16;
            const size_t gidx = (size_t)(kb * 64 + row) * HD + lc;
            float4 vk = *(const float4*)(kbase + gidx);
            Ks[row][lc + 0] = vk.x; Ks[row][lc + 1] = vk.y;
            Ks[row][lc + 2] = vk.z; Ks[row][lc + 3] = vk.w;
            float4 vv = *(const float4*)(vbase + gidx);
            Vs[row][lc + 0] = vv.x; Vs[row][lc + 1] = vv.y;
            Vs[row][lc + 2] = vv.z; Vs[row][lc + 3] = vv.w;
        }
        __syncthreads();

        // S = Q K^T * SCALE  (4x4 per thread)
        float s[4][4] = {};
        #pragma unroll 16
        for (int d = 0; d < 64; d++) {
            float a[4], kk[4];
            #pragma unroll
            for (int i = 0; i < 4; i++) a[i] = Qs[r0 + i][d];
            #pragma unroll
            for (int j = 0; j < 4; j++) kk[j] = Ks[c0 + j][d];
            #pragma unroll
            for (int i = 0; i < 4; i++)
                #pragma unroll
                for (int j = 0; j < 4; j++)
                    s[i][j] = fmaf(a[i], kk[j], s[i][j]);
        }

        // Online softmax: row reductions across the 16 threads sharing ty
        float p[4][4], factor[4];
        #pragma unroll
        for (int i = 0; i < 4; i++) {
            float mx = -1e30f;
            #pragma unroll
            for (int j = 0; j < 4; j++) {
                s[i][j] *= SCALE;
                mx = fmaxf(mx, s[i][j]);
            }
            #pragma unroll
            for (int w = 8; w >= 1; w >>= 1)
                mx = fmaxf(mx, __shfl_xor_sync(0xffffffffu, mx, w));
            const float mnew = fmaxf(mi[i], mx);
            factor[i] = __expf(mi[i] - mnew);
            float rs = 0.f;
            #pragma unroll
            for (int j = 0; j < 4; j++) {
                p[i][j] = __expf(s[i][j] - mnew);
                rs += p[i][j];
            }
            #pragma unroll
            for (int w = 8; w >= 1; w >>= 1)
                rs += __shfl_xor_sync(0xffffffffu, rs, w);
            li[i] = li[i] * factor[i] + rs;
            mi[i] = mnew;
            #pragma unroll
            for (int j = 0; j < 4; j++) o[i][j] *= factor[i];
        }
        __syncthreads();   // everyone done reading Ks -> safe to overwrite with P

        #pragma unroll
        for (int i = 0; i < 4; i++)
            #pragma unroll
            for (int j = 0; j < 4; j++)
                Ks[r0 + i][c0 + j] = p[i][j];
        __syncthreads();

        // O += P @ V
        #pragma unroll 16
        for (int jk = 0; jk < 64; jk++) {
            float pi[4], vv[4];
            #pragma unroll
            for (int i = 0; i < 4; i++) pi[i] = Ks[r0 + i][jk];
            #pragma unroll
            for (int j = 0; j < 4; j++) vv[j] = Vs[jk][c0 + j];
            #pragma unroll
            for (int i = 0; i < 4; i++)
                #pragma unroll
                for (int j = 0; j < 4; j++)
                    o[i][j] = fmaf(pi[i], vv[j], o[i][j]);
        }
        __syncthreads();   // done with P/V before next tile load
    }

    // Normalize + store to head-split scratch
    #pragma unroll
    for (int i = 0; i < 4; i++) {
        const float inv = 1.0f / li[i];
        const int qrow = qt * 64 + r0 + i;
        #pragma unroll
        for (int j = 0; j < 4; j++)
            O[((size_t)bh * SS + qrow) * HD + c0 + j] = o[i][j] * inv;
    }
}

// ---------------------------------------------------------------------------
extern "C" void kernel_launch(void* const* d_in, const int* in_sizes, int n_in,
                              void* d_out, int out_size)
{
    const float* x  = (const float*)d_in[0];
    const float* wq = (const float*)d_in[1];
    const float* wk = (const float*)d_in[2];
    const float* wv = (const float*)d_in[3];
    const float* wo = (const float*)d_in[4];
    const float* bo = (const float*)d_in[5];
    float* out = (float*)d_out;

    float *qp, *kp, *vp, *ap;
    cudaGetSymbolAddress((void**)&qp, g_q);
    cudaGetSymbolAddress((void**)&kp, g_k);
    cudaGetSymbolAddress((void**)&vp, g_v);
    cudaGetSymbolAddress((void**)&ap, g_ao);

    const dim3 gg(BB * SS / 64, DD / 64);   // (256, 4)
    gemm_kernel<false, true, false><<<gg, 256>>>(x, wq, nullptr, qp);
    gemm_kernel<false, true, false><<<gg, 256>>>(x, wk, nullptr, kp);
    gemm_kernel<false, true, false><<<gg, 256>>>(x, wv, nullptr, vp);

    const size_t smem = 3 * 64 * 68 * sizeof(float);   // 52224 B
    cudaFuncSetAttribute(attn_kernel, cudaFuncAttributeMaxDynamicSharedMemorySize, (int)smem);
    attn_kernel<<<dim3(SS / 64, HH, BB), 256, smem>>>(qp, kp, vp, ap);

    gemm_kernel<true, false, true><<<gg, 256>>>(ap, wo, bo, out);
}

// round 12
// speedup vs baseline: 1.0001x; 1.0001x over previous
#include <cuda_runtime.h>
#include <cuda_bf16.h>

// Problem constants
#define BB 4
#define SS 4096
#define DD 256
#define HH 4
#define HD 64
#define SCALE 0.125f   // 64^-0.5

// Scratch (allocation-free rule: __device__ globals)
__device__ float g_q[BB*HH*SS*HD];
__device__ float g_k[BB*HH*SS*HD];
__device__ float g_v[BB*HH*SS*HD];
__device__ float g_ao[BB*HH*SS*HD];

// ---------------------------------------------------------------------------
// GEMM: C[m,n] = sum_k A[m,k] * W[n,k] (+ bias[n])
// M = 16384 (m = b*SS + s), N = 256, K = 256.
// HSA: A is head-split [B,H,S,HD] (k -> h= k/64, d = k%64)
// HSC: C written head-split [B,H,S,HD] (n -> h = n/64, d = n%64)
// Block: 256 threads, 64x64 output tile, 4x4 per-thread micro-tile.
// ---------------------------------------------------------------------------
template<bool HSA, bool HSC, bool BIAS>
__global__ void __launch_bounds__(256) gemm_kernel(
    const float* __restrict__ A, const float* __restrict__ W,
    const float* __restrict__ bias, float* __restrict__ C)
{
    __shared__ float As[64][68];
    __shared__ float Wsh[64][68];

    const int tid = threadIdx.x;
    const int tx = tid & 15;        // 0..15
    const int ty = tid >> 4;        // 0..15
    const int m0 = blockIdx.x * 64;
    const int n0 = blockIdx.y * 64;
    const int lr = ty;              // loader row base
    const int lc = tx * 4;          // loader col

    float acc[4][4] = {};

    for (int kc = 0; kc < 256; kc += 64) {
        #pragma unroll
        for (int rr = 0; rr < 4; rr++) {
            const int row = lr + rr * 16;
            // A tile
            const int m = m0 + row;
            const float* asrc;
            if (HSA) {
                const int b = m >> 12, s = m & 4095;
                const int h = kc >> 6;
                asrc = A + (((b * HH + h) * SS + s) * HD + lc);
            } else {
                asrc = A + ((size_t)m * 256 + kc + lc);
            }
            float4 va = *(const float4*)asrc;
            As[row][lc + 0] = va.x; As[row][lc + 1] = va.y;
            As[row][lc + 2] = va.z; As[row][lc + 3] = va.w;
            // W tile: row n0+row, cols kc+lc
            float4 vw = *(const float4*)(W + (size_t)(n0 + row) * 256 + kc + lc);
            Wsh[row][lc + 0] = vw.x; Wsh[row][lc + 1] = vw.y;
            Wsh[row][lc + 2] = vw.z; Wsh[row][lc + 3] = vw.w;
        }
        __syncthreads();

        const int r0 = ty * 4, c0 = tx * 4;
        #pragma unroll 16
        for (int k = 0; k < 64; k++) {
            float a[4], w[4];
            #pragma unroll
            for (int i = 0; i < 4; i++) a[i] = As[r0 + i][k];
            #pragma unroll
            for (int j = 0; j < 4; j++) w[j] = Wsh[c0 + j][k];
            #pragma unroll
            for (int i = 0; i < 4; i++)
                #pragma unroll
                for (int j = 0; j < 4; j++)
                    acc[i][j] = fmaf(a[i], w[j], acc[i][j]);
        }
        __syncthreads();
    }

    const int r0 = ty * 4, c0 = tx * 4;
    #pragma unroll
    for (int i = 0; i < 4; i++) {
        const int m = m0 + r0 + i;
        #pragma unroll
        for (int j = 0; j < 4; j++) {
            const int n = n0 + c0 + j;
            float v = acc[i][j];
            if (BIAS) v += bias[n];
            if (HSC) {
                const int b = m >> 12, s = m & 4095;
                const int h = n >> 6, d = n & 63;
                C[((b * HH + h) * SS + s) * HD + d] = v;
            } else {
                C[(size_t)m * 256 + n] = v;
            }
        }
    }
}

// ---------------------------------------------------------------------------
// Flash attention: one block = 64 queries for one (b, h).
// Tiles: Q[64][64] persistent, K[64][64] (re-used as P after scores), V[64][64].
// 256 threads, 4x4 micro-tiles, warp-shuffle row reductions (16-lane groups).
// ---------------------------------------------------------------------------
__global__ void __launch_bounds__(256) attn_kernel(
    const float* __restrict__ Q, const float* __restrict__ K,
    const float* __restrict__ V, float* __restrict__ O)
{
    extern __shared__ float sm[];
    float (*Qs)[68] = (float (*)[68])sm;
    float (*Ks)[68] = (float (*)[68])(sm + 64 * 68);       // re-used as P
    float (*Vs)[68] = (float (*)[68])(sm + 2 * 64 * 68);

    const int tid = threadIdx.x;
    const int tx = tid & 15, ty = tid >> 4;
    const int qt = blockIdx.x;     // query tile
    const int h  = blockIdx.y;
    const int b  = blockIdx.z;
    const int bh = b * HH + h;
    const float* qbase = Q + ((size_t)bh * SS) * HD;
    const float* kbase = K + ((size_t)bh * SS) * HD;
    const float* vbase = V + ((size_t)bh * SS) * HD;

    const int lr = ty, lc = tx * 4;
    const int r0 = ty * 4, c0 = tx * 4;

    // Load Q tile (rows qt*64 .. +63)
    #pragma unroll
    for (int rr = 0; rr < 4; rr++) {
        const int row = lr + rr * 16;
        float4 vq = *(const float4*)(qbase + (size_t)(qt * 64 + row) * HD + lc);
        Qs[row][lc + 0] = vq.x; Qs[row][lc + 1] = vq.y;
        Qs[row][lc + 2] = vq.z; Qs[row][lc + 3] = vq.w;
    }

    float mi[4], li[4], o[4][4];
    #pragma unroll
    for (int i = 0; i < 4; i++) {
        mi[i] = -1e30f; li[i] = 0.f;
        #pragma unroll
        for (int j = 0; j < 4; j++) o[i][j] = 0.f;
    }
    __syncthreads();

    for (int kb = 0; kb < SS / 64; kb++) {
        // Load K, V tiles
        #pragma unroll
        for (int rr = 0; rr < 4; rr++) {
            const int row = lr + rr * 16;
            const size_t gidx = (size_t)(kb * 64 + row) * HD + lc;
            float4 vk = *(const float4*)(kbase + gidx);
            Ks[row][lc + 0] = vk.x; Ks[row][lc + 1] = vk.y;
            Ks[row][lc + 2] = vk.z; Ks[row][lc + 3] = vk.w;
            float4 vv = *(const float4*)(vbase + gidx);
            Vs[row][lc + 0] = vv.x; Vs[row][lc + 1] = vv.y;
            Vs[row][lc + 2] = vv.z; Vs[row][lc + 3] = vv.w;
        }
        __syncthreads();

        // S = Q K^T * SCALE  (4x4 per thread)
        float s[4][4] = {};
        #pragma unroll 16
        for (int d = 0; d < 64; d++) {
            float a[4], kk[4];
            #pragma unroll
            for (int i = 0; i < 4; i++) a[i] = Qs[r0 + i][d];
            #pragma unroll
            for (int j = 0; j < 4; j++) kk[j] = Ks[c0 + j][d];
            #pragma unroll
            for (int i = 0; i < 4; i++)
                #pragma unroll
                for (int j = 0; j < 4; j++)
                    s[i][j] = fmaf(a[i], kk[j], s[i][j]);
        }

        // Online softmax: row reductions across the 16 threads sharing ty
        float p[4][4], factor[4];
        #pragma unroll
        for (int i = 0; i < 4; i++) {
            float mx = -1e30f;
            #pragma unroll
            for (int j = 0; j < 4; j++) {
                s[i][j] *= SCALE;
                mx = fmaxf(mx, s[i][j]);
            }
            #pragma unroll
            for (int w = 8; w >= 1; w >>= 1)
                mx = fmaxf(mx, __shfl_xor_sync(0xffffffffu, mx, w));
            const float mnew = fmaxf(mi[i], mx);
            factor[i] = __expf(mi[i] - mnew);
            float rs = 0.f;
            #pragma unroll
            for (int j = 0; j < 4; j++) {
                p[i][j] = __expf(s[i][j] - mnew);
                rs += p[i][j];
            }
            #pragma unroll
            for (int w = 8; w >= 1; w >>= 1)
                rs += __shfl_xor_sync(0xffffffffu, rs, w);
            li[i] = li[i] * factor[i] + rs;
            mi[i] = mnew;
            #pragma unroll
            for (int j = 0; j < 4; j++) o[i][j] *= factor[i];
        }
        __syncthreads();   // everyone done reading Ks -> safe to overwrite with P

        #pragma unroll
        for (int i = 0; i < 4; i++)
            #pragma unroll
            for (int j = 0; j < 4; j++)
                Ks[r0 + i][c0 + j] = p[i][j];
        __syncthreads();

        // O += P @ V
        #pragma unroll 16
        for (int jk = 0; jk < 64; jk++) {
            float pi[4], vv[4];
            #pragma unroll
            for (int i = 0; i < 4; i++) pi[i] = Ks[r0 + i][jk];
            #pragma unroll
            for (int j = 0; j < 4; j++) vv[j] = Vs[jk][c0 + j];
            #pragma unroll
            for (int i = 0; i < 4; i++)
                #pragma unroll
                for (int j = 0; j < 4; j++)
                    o[i][j] = fmaf(pi[i], vv[j], o[i][j]);
        }
        __syncthreads();   // done with P/V before next tile load
    }

    // Normalize + store to head-split scratch
    #pragma unroll
    for (int i = 0; i < 4; i++) {
        const float inv = 1.0f / li[i];
        const int qrow = qt * 64 + r0 + i;
        #pragma unroll
        for (int j = 0; j < 4; j++)
            O[((size_t)bh * SS + qrow) * HD + c0 + j] = o[i][j] * inv;
    }
}

// ---------------------------------------------------------------------------
extern "C" void kernel_launch(void* const* d_in, const int* in_sizes, int n_in,
                              void* d_out, int out_size)
{
    const float* x  = (const float*)d_in[0];
    const float* wq = (const float*)d_in[1];
    const float* wk = (const float*)d_in[2];
    const float* wv = (const float*)d_in[3];
    const float* wo = (const float*)d_in[4];
    const float* bo = (const float*)d_in[5];
    float* out = (float*)d_out;

    float *qp, *kp, *vp, *ap;
    cudaGetSymbolAddress((void**)&qp, g_q);
    cudaGetSymbolAddress((void**)&kp, g_k);
    cudaGetSymbolAddress((void**)&vp, g_v);
    cudaGetSymbolAddress((void**)&ap, g_ao);

    const dim3 gg(BB * SS / 64, DD / 64);   // (256, 4)
    gemm_kernel<false, true, false><<<gg, 256>>>(x, wq, nullptr, qp);
    gemm_kernel<false, true, false><<<gg, 256>>>(x, wk, nullptr, kp);
    gemm_kernel<false, true, false><<<gg, 256>>>(x, wv, nullptr, vp);

    const size_t smem = 3 * 64 * 68 * sizeof(float);   // 52224 B
    cudaFuncSetAttribute(attn_kernel, cudaFuncAttributeMaxDynamicSharedMemorySize, (int)smem);
    attn_kernel<<<dim3(SS / 64, HH, BB), 256, smem>>>(qp, kp, vp, ap);

    gemm_kernel<true, false, true><<<gg, 256>>>(ap, wo, bo, out);
}

// round 13
// speedup vs baseline: 1.0015x; 1.0014x over previous
#include <cuda_runtime.h>
#include <cuda_bf16.h>

// Problem constants
#define BB 4
#define SS 4096
#define DD 256
#define HH 4
#define HD 64
#define SCALE 0.125f   // 64^-0.5

// Scratch (allocation-free rule: __device__ globals)
__device__ float g_q[BB*HH*SS*HD];
__device__ float g_k[BB*HH*SS*HD];
__device__ float g_v[BB*HH*SS*HD];
__device__ float g_ao[BB*HH*SS*HD];

// ---------------------------------------------------------------------------
// GEMM: C[m,n] = sum_k A[m,k] * W[n,k] (+ bias[n])
// M = 16384 (m = b*SS + s), N = 256, K = 256.
// HSA: A is head-split [B,H,S,HD] (k -> h= k/64, d = k%64)
// HSC: C written head-split [B,H,S,HD] (n -> h = n/64, d = n%64)
// Block: 256 threads, 64x64 output tile, 4x4 per-thread micro-tile.
// ---------------------------------------------------------------------------
template<bool HSA, bool HSC, bool BIAS>
__global__ void __launch_bounds__(256) gemm_kernel(
    const float* __restrict__ A, const float* __restrict__ W,
    const float* __restrict__ bias, float* __restrict__ C)
{
    __shared__ float As[64][68];
    __shared__ float Wsh[64][68];

    const int tid = threadIdx.x;
    const int tx = tid & 15;        // 0..15
    const int ty = tid >> 4;        // 0..15
    const int m0 = blockIdx.x * 64;
    const int n0 = blockIdx.y * 64;
    const int lr = ty;              // loader row base
    const int lc = tx * 4;          // loader col

    float acc[4][4] = {};

    for (int kc = 0; kc < 256; kc += 64) {
        #pragma unroll
        for (int rr = 0; rr < 4; rr++) {
            const int row = lr + rr * 16;
            // A tile
            const int m = m0 + row;
            const float* asrc;
            if (HSA) {
                const int b = m >> 12, s = m & 4095;
                const int h = kc >> 6;
                asrc = A + (((b * HH + h) * SS + s) * HD + lc);
            } else {
                asrc = A + ((size_t)m * 256 + kc + lc);
            }
            float4 va = *(const float4*)asrc;
            As[row][lc + 0] = va.x; As[row][lc + 1] = va.y;
            As[row][lc + 2] = va.z; As[row][lc + 3] = va.w;
            // W tile: row n0+row, cols kc+lc
            float4 vw = *(const float4*)(W + (size_t)(n0 + row) * 256 + kc + lc);
            Wsh[row][lc + 0] = vw.x; Wsh[row][lc + 1] = vw.y;
            Wsh[row][lc + 2] = vw.z; Wsh[row][lc + 3] = vw.w;
        }
        __syncthreads();

        const int r0 = ty * 4, c0 = tx * 4;
        #pragma unroll 16
        for (int k = 0; k < 64; k++) {
            float a[4], w[4];
            #pragma unroll
            for (int i = 0; i < 4; i++) a[i] = As[r0 + i][k];
            #pragma unroll
            for (int j = 0; j < 4; j++) w[j] = Wsh[c0 + j][k];
            #pragma unroll
            for (int i = 0; i < 4; i++)
                #pragma unroll
                for (int j = 0; j < 4; j++)
                    acc[i][j] = fmaf(a[i], w[j], acc[i][j]);
        }
        __syncthreads();
    }

    const int r0 = ty * 4, c0 = tx * 4;
    #pragma unroll
    for (int i = 0; i < 4; i++) {
        const int m = m0 + r0 + i;
        #pragma unroll
        for (int j = 0; j < 4; j++) {
            const int n = n0 + c0 + j;
            float v = acc[i][j];
            if (BIAS) v += bias[n];
            if (HSC) {
                const int b = m >> 12, s = m & 4095;
                const int h = n >> 6, d = n & 63;
                C[((b * HH + h) * SS + s) * HD + d] = v;
            } else {
                C[(size_t)m * 256 + n] = v;
            }
        }
    }
}

// ---------------------------------------------------------------------------
// Flash attention: one block = 64 queries for one (b, h).
// Tiles: Q[64][64] persistent, K[64][64] (re-used as P after scores), V[64][64].
// 256 threads, 4x4 micro-tiles, warp-shuffle row reductions (16-lane groups).
// ---------------------------------------------------------------------------
__global__ void __launch_bounds__(256) attn_kernel(
    const float* __restrict__ Q, const float* __restrict__ K,
    const float* __restrict__ V, float* __restrict__ O)
{
    extern __shared__ float sm[];
    float (*Qs)[68] = (float (*)[68])sm;
    float (*Ks)[68] = (float (*)[68])(sm + 64 * 68);       // re-used as P
    float (*Vs)[68] = (float (*)[68])(sm + 2 * 64 * 68);

    const int tid = threadIdx.x;
    const int tx = tid & 15, ty = tid >> 4;
    const int qt = blockIdx.x;     // query tile
    const int h  = blockIdx.y;
    const int b  = blockIdx.z;
    const int bh = b * HH + h;
    const float* qbase = Q + ((size_t)bh * SS) * HD;
    const float* kbase = K + ((size_t)bh * SS) * HD;
    const float* vbase = V + ((size_t)bh * SS) * HD;

    const int lr = ty, lc = tx * 4;
    const int r0 = ty * 4, c0 = tx * 4;

    // Load Q tile (rows qt*64 .. +63)
    #pragma unroll
    for (int rr = 0; rr < 4; rr++) {
        const int row = lr + rr * 16;
        float4 vq = *(const float4*)(qbase + (size_t)(qt * 64 + row) * HD + lc);
        Qs[row][lc + 0] = vq.x; Qs[row][lc + 1] = vq.y;
        Qs[row][lc + 2] = vq.z; Qs[row][lc + 3] = vq.w;
    }

    float mi[4], li[4], o[4][4];
    #pragma unroll
    for (int i = 0; i < 4; i++) {
        mi[i] = -1e30f; li[i] = 0.f;
        #pragma unroll
        for (int j = 0; j < 4; j++) o[i][j] = 0.f;
    }
    __syncthreads();

    for (int kb = 0; kb < SS / 64; kb++) {
        // Load K, V tiles
        #pragma unroll
        for (int rr = 0; rr < 4; rr++) {
            const int row = lr + rr * 16;
            const size_t gidx = (size_t)(kb * 64 + row) * HD + lc;
            float4 vk = *(const float4*)(kbase + gidx);
            Ks[row][lc + 0] = vk.x; Ks[row][lc + 1] = vk.y;
            Ks[row][lc + 2] = vk.z; Ks[row][lc + 3] = vk.w;
            float4 vv = *(const float4*)(vbase + gidx);
            Vs[row][lc + 0] = vv.x; Vs[row][lc + 1] = vv.y;
            Vs[row][lc + 2] = vv.z; Vs[row][lc + 3] = vv.w;
        }
        __syncthreads();

        // S = Q K^T * SCALE  (4x4 per thread)
        float s[4][4] = {};
        #pragma unroll 16
        for (int d = 0; d < 64; d++) {
            float a[4], kk[4];
            #pragma unroll
            for (int i = 0; i < 4; i++) a[i] = Qs[r0 + i][d];
            #pragma unroll
            for (int j = 0; j < 4; j++) kk[j] = Ks[c0 + j][d];
            #pragma unroll
            for (int i = 0; i < 4; i++)
                #pragma unroll
                for (int j = 0; j < 4; j++)
                    s[i][j] = fmaf(a[i], kk[j], s[i][j]);
        }

        // Online softmax: row reductions across the 16 threads sharing ty
        float p[4][4], factor[4];
        #pragma unroll
        for (int i = 0; i < 4; i++) {
            float mx = -1e30f;
            #pragma unroll
            for (int j = 0; j < 4; j++) {
                s[i][j] *= SCALE;
                mx = fmaxf(mx, s[i][j]);
            }
            #pragma unroll
            for (int w = 8; w >= 1; w >>= 1)
                mx = fmaxf(mx, __shfl_xor_sync(0xffffffffu, mx, w));
            const float mnew = fmaxf(mi[i], mx);
            factor[i] = __expf(mi[i] - mnew);
            float rs = 0.f;
            #pragma unroll
            for (int j = 0; j < 4; j++) {
                p[i][j] = __expf(s[i][j] - mnew);
                rs += p[i][j];
            }
            #pragma unroll
            for (int w = 8; w >= 1; w >>= 1)
                rs += __shfl_xor_sync(0xffffffffu, rs, w);
            li[i] = li[i] * factor[i] + rs;
            mi[i] = mnew;
            #pragma unroll
            for (int j = 0; j < 4; j++) o[i][j] *= factor[i];
        }
        __syncthreads();   // everyone done reading Ks -> safe to overwrite with P

        #pragma unroll
        for (int i = 0; i < 4; i++)
            #pragma unroll
            for (int j = 0; j < 4; j++)
                Ks[r0 + i][c0 + j] = p[i][j];
        __syncthreads();

        // O += P @ V
        #pragma unroll 16
        for (int jk = 0; jk < 64; jk++) {
            float pi[4], vv[4];
            #pragma unroll
            for (int i = 0; i < 4; i++) pi[i] = Ks[r0 + i][jk];
            #pragma unroll
            for (int j = 0; j < 4; j++) vv[j] = Vs[jk][c0 + j];
            #pragma unroll
            for (int i = 0; i < 4; i++)
                #pragma unroll
                for (int j = 0; j < 4; j++)
                    o[i][j] = fmaf(pi[i], vv[j], o[i][j]);
        }
        __syncthreads();   // done with P/V before next tile load
    }

    // Normalize + store to head-split scratch
    #pragma unroll
    for (int i = 0; i < 4; i++) {
        const float inv = 1.0f / li[i];
        const int qrow = qt * 64 + r0 + i;
        #pragma unroll
        for (int j = 0; j < 4; j++)
            O[((size_t)bh * SS + qrow) * HD + c0 + j] = o[i][j] * inv;
    }
}

// ---------------------------------------------------------------------------
extern "C" void kernel_launch(void* const* d_in, const int* in_sizes, int n_in,
                              void* d_out, int out_size)
{
    const float* x  = (const float*)d_in[0];
    const float* wq = (const float*)d_in[1];
    const float* wk = (const float*)d_in[2];
    const float* wv = (const float*)d_in[3];
    const float* wo = (const float*)d_in[4];
    const float* bo = (const float*)d_in[5];
    float* out = (float*)d_out;

    float *qp, *kp, *vp, *ap;
    cudaGetSymbolAddress((void**)&qp, g_q);
    cudaGetSymbolAddress((void**)&kp, g_k);
    cudaGetSymbolAddress((void**)&vp, g_v);
    cudaGetSymbolAddress((void**)&ap, g_ao);

    const dim3 gg(BB * SS / 64, DD / 64);   // (256, 4)
    gemm_kernel<false, true, false><<<gg, 256>>>(x, wq, nullptr, qp);
    gemm_kernel<false, true, false><<<gg, 256>>>(x, wk, nullptr, kp);
    gemm_kernel<false, true, false><<<gg, 256>>>(x, wv, nullptr, vp);

    const size_t smem = 3 * 64 * 68 * sizeof(float);   // 52224 B
    cudaFuncSetAttribute(attn_kernel, cudaFuncAttributeMaxDynamicSharedMemorySize, (int)smem);
    attn_kernel<<<dim3(SS / 64, HH, BB), 256, smem>>>(qp, kp, vp, ap);

    gemm_kernel<true, false, true><<<gg, 256>>>(ap, wo, bo, out);
}